// round 9
// baseline (speedup 1.0000x reference)
#include <cuda_runtime.h>
#include <math.h>

typedef unsigned long long u64;

#define NG 8
#define NT 2048
#define NH 2048
#define NE 8
#define CAP 320
#define NTOK (NG * NT)        // 16384
#define TPBK 32               // tokens per block (8 warps * 4)
#define NBLK (NTOK / TPBK)    // 512 (3 CTAs/SM resident -> 24 warps/SM)
#define BPG (NBLK / NG)       // 64 blocks per group
#define THREADS 256
#define NITER 16              // H chunks of 128 floats

// scratch: argmax ids; per-group completion counters.
// g_cnt is tested modulo BPG -> never needs resetting across graph replays.
__device__ unsigned char g_expert_id[NTOK];
__device__ unsigned int  g_cnt[NG];

__device__ __forceinline__ void fma2(u64& acc, u64 a, u64 b) {
    asm("fma.rn.f32x2 %0, %1, %2, %0;" : "+l"(acc) : "l"(a), "l"(b));
}
__device__ __forceinline__ u64 add2(u64 a, u64 b) {
    u64 r; asm("add.rn.f32x2 %0, %1, %2;" : "=l"(r) : "l"(a), "l"(b));
    return r;
}
__device__ __forceinline__ u64 pack2(float lo, float hi) {
    u64 r; asm("mov.b64 %0, {%1, %2};" : "=l"(r) : "f"(lo), "f"(hi));
    return r;
}
__device__ __forceinline__ u64 dup2(float v) { return pack2(v, v); }
__device__ __forceinline__ void unpack2(u64 v, float& lo, float& hi) {
    asm("mov.b64 {%0, %1}, %2;" : "=f"(lo), "=f"(hi) : "l"(v));
}

// ---------------------------------------------------------------------------
// Capacity epilogue: per-group inclusive cumsum of assignments; zero the
// over-capacity one-hot entries. Run by the LAST router block of each group.
// ---------------------------------------------------------------------------
__device__ void capacity_epilogue(int g, float* __restrict__ out) {
    const int tid = threadIdx.x;           // 256
    const int lane = tid & 31, wrp = tid >> 5;

    u64 ids = ((const u64*)g_expert_id)[g * (NT / 8) + tid];

    int c[NE], s[NE];
#pragma unroll
    for (int e = 0; e < NE; e++) c[e] = 0;
#pragma unroll
    for (int i = 0; i < 8; i++) {
        int e = (int)((ids >> (8 * i)) & 0xFFULL);
#pragma unroll
        for (int ee = 0; ee < NE; ee++) c[ee] += (e == ee);
    }
#pragma unroll
    for (int e = 0; e < NE; e++) s[e] = c[e];
#pragma unroll
    for (int off = 1; off < 32; off <<= 1) {
#pragma unroll
        for (int e = 0; e < NE; e++) {
            int v = __shfl_up_sync(0xffffffffu, s[e], off);
            if (lane >= off) s[e] += v;
        }
    }

    __shared__ int wt[8][NE];
    if (lane == 31) {
#pragma unroll
        for (int e = 0; e < NE; e++) wt[wrp][e] = s[e];
    }
    __syncthreads();
    if (tid < NE) {            // exclusive scan of 8 warp totals
        int run = 0;
#pragma unroll
        for (int w = 0; w < 8; w++) {
            int v = wt[w][tid];
            wt[w][tid] = run;
            run += v;
        }
    }
    __syncthreads();

    int base[NE];
#pragma unroll
    for (int e = 0; e < NE; e++) base[e] = (s[e] - c[e]) + wt[wrp][e];

    int run2[NE];
#pragma unroll
    for (int e = 0; e < NE; e++) run2[e] = 0;

    const size_t tok0 = (size_t)g * NT + (size_t)tid * 8;
#pragma unroll
    for (int i = 0; i < 8; i++) {
        int e = (int)((ids >> (8 * i)) & 0xFFULL);
#pragma unroll
        for (int ee = 0; ee < NE; ee++) {
            int inc = (e == ee);
            run2[ee] += inc;
            if (inc && (base[ee] + run2[ee] > CAP))
                out[(tok0 + i) * NE + ee] = 0.0f;
        }
    }
}

// ---------------------------------------------------------------------------
// Router kernel, lane-parity paired:
//   warp owns 4 tokens; even lanes handle tokens {0,2}, odd lanes {1,3}.
//   Lane pair (2k, 2k+1) shares h-slice h = i*128 + k*8 + j (j=0..7)
//   -> W LDS.64 reads are 2-lane broadcasts (half crossbar bytes),
//   -> acc is only 16 regs/thread (2 tokens x 4 expert-pair words).
// Distance-1 register double buffer keeps next iter's 4 LDG.128 in flight
// during compute. 3 CTAs/SM (85-reg cap) -> 24 warps for latency hiding.
// ---------------------------------------------------------------------------
__global__ __launch_bounds__(THREADS, 3)
void router_kernel(const float4* __restrict__ hs4,
                   const float* __restrict__ W,
                   const float* __restrict__ bias,
                   float* __restrict__ out) {
    extern __shared__ char smem[];
    u64*   shw      = (u64*)smem;                       // 8192 u64 = 64 KB
    float* sh_logit = (float*)(shw + NE * NH / 2);      // 32*9
    float* sh_bias  = sh_logit + TPBK * 9;              // 8
    int*   sh_arg   = (int*)(sh_bias + 8);              // 32

    const int tid  = threadIdx.x;
    const int lane = tid & 31, warp = tid >> 5;
    const int s = lane & 1;        // token parity owned by this lane
    const int k = lane >> 1;       // h-slice index (0..15)

    // W fill: coalesced LDG.128 over W, scattered STS.32 into pair-word
    // layout: u64 word widx = ((i*8 + j)*4 + p)*16 + k holds
    // (W[2p][h], W[2p+1][h]) with h = i*128 + k*8 + j.
    {
        float* shwf = (float*)shw;
        const float4* W4 = (const float4*)W;
#pragma unroll
        for (int q = 0; q < 16; q++) {
            int idx4 = tid + q * THREADS;            // 0..4095
            float4 v = W4[idx4];
#pragma unroll
            for (int c = 0; c < 4; c++) {
                int f = idx4 * 4 + c;                // e*2048 + h
                int e = f >> 11, h = f & 2047;
                int hi = h >> 7, hk = (h >> 3) & 15, hj = h & 7;
                int p = e >> 1, half = e & 1;
                int widx = ((hi * 8 + hj) * 4 + p) * 16 + hk;
                float val = (c == 0) ? v.x : (c == 1) ? v.y
                          : (c == 2) ? v.z : v.w;
                shwf[widx * 2 + half] = val;
            }
        }
    }
    if (tid < 8) sh_bias[tid] = bias[tid];
    __syncthreads();

    const int tokbase = blockIdx.x * TPBK + warp * 4;
    // lane's two token rows: token (tokbase+s) and (tokbase+s+2)
    const float4* xr0 = hs4 + (size_t)(tokbase + s) * (NH / 4);
    const float4* xr1 = xr0 + 2 * (NH / 4);

    u64 acc[2][4];
#pragma unroll
    for (int t = 0; t < 2; t++)
#pragma unroll
        for (int p = 0; p < 4; p++) acc[t][p] = 0ULL;

    // double buffer: [slot][t*2 + chunk] ; chunks c0 = i*32+2k, c1 = c0+1
    float4 buf[2][4];
    {
        int c0 = 2 * k;
        buf[0][0] = xr0[c0];  buf[0][1] = xr0[c0 + 1];
        buf[0][2] = xr1[c0];  buf[0][3] = xr1[c0 + 1];
    }

#pragma unroll
    for (int i = 0; i < NITER; i++) {
        const int cs = i & 1, ns = cs ^ 1;
        if (i + 1 < NITER) {               // issue i+1 BEFORE computing i
            int c0 = (i + 1) * 32 + 2 * k;
            buf[ns][0] = xr0[c0];  buf[ns][1] = xr0[c0 + 1];
            buf[ns][2] = xr1[c0];  buf[ns][3] = xr1[c0 + 1];
        }

#pragma unroll
        for (int j = 0; j < 8; j++) {
            u64 w0 = shw[((i * 8 + j) * 4 + 0) * 16 + k];
            u64 w1 = shw[((i * 8 + j) * 4 + 1) * 16 + k];
            u64 w2 = shw[((i * 8 + j) * 4 + 2) * 16 + k];
            u64 w3 = shw[((i * 8 + j) * 4 + 3) * 16 + k];
#pragma unroll
            for (int t = 0; t < 2; t++) {
                const float4& xc = buf[cs][t * 2 + (j >> 2)];
                float xs = ((j & 3) == 0) ? xc.x : ((j & 3) == 1) ? xc.y
                         : ((j & 3) == 2) ? xc.z : xc.w;
                u64 xd = dup2(xs);
                fma2(acc[t][0], xd, w0);
                fma2(acc[t][1], xd, w1);
                fma2(acc[t][2], xd, w2);
                fma2(acc[t][3], xd, w3);
            }
        }
    }

    // reduce over the 16 lane-pairs (parity-preserving butterfly)
#pragma unroll
    for (int off = 2; off < 32; off <<= 1) {
#pragma unroll
        for (int t = 0; t < 2; t++)
#pragma unroll
            for (int p = 0; p < 4; p++)
                acc[t][p] = add2(acc[t][p],
                                 __shfl_xor_sync(0xffffffffu, acc[t][p], off));
    }
    if (lane < 2) {       // lane 0: tokens 0,2 ; lane 1: tokens 1,3
#pragma unroll
        for (int t = 0; t < 2; t++)
#pragma unroll
            for (int p = 0; p < 4; p++) {
                float lo, hi;
                unpack2(acc[t][p], lo, hi);
                int lt = warp * 4 + s + 2 * t;
                sh_logit[lt * 9 + 2 * p]     = lo + sh_bias[2 * p];
                sh_logit[lt * 9 + 2 * p + 1] = hi + sh_bias[2 * p + 1];
            }
    }
    __syncthreads();

    // softmax stats + argmax (first-max semantics matches jnp.argmax)
    if (tid < TPBK) {
        const float* l = sh_logit + tid * 9;
        float best = l[0]; int bi = 0;
#pragma unroll
        for (int e = 1; e < NE; e++) {
            float v = l[e];
            if (v > best) { best = v; bi = e; }
        }
        float ssum = 0.f;
#pragma unroll
        for (int e = 0; e < NE; e++) ssum += expf(l[e] - best);
        sh_arg[tid] = bi;
        int gt = blockIdx.x * TPBK + tid;
        out[(size_t)NTOK * NE + gt] = 1.0f / ssum;   // max router prob
        g_expert_id[gt] = (unsigned char)bi;
    }
    __syncthreads();

    // one-hot (pre-capacity) + logits: thread = (token t, expert e)
    {
        int t = tid >> 3, e = tid & 7;
        int gt = blockIdx.x * TPBK + t;
        out[(size_t)gt * NE + e] = (e == sh_arg[t]) ? 1.0f : 0.0f;
        out[(size_t)NTOK * NE + NTOK + (size_t)gt * NE + e] = sh_logit[t * 9 + e];
    }

    // ---- fused capacity epilogue: last block of each group runs it ----
    __threadfence();
    __syncthreads();
    __shared__ int s_last;
    if (tid == 0) {
        unsigned int v = atomicAdd(&g_cnt[blockIdx.x / BPG], 1u);
        s_last = ((v & (BPG - 1)) == (BPG - 1));
    }
    __syncthreads();
    if (s_last) {
        __threadfence();   // acquire: see all group blocks' writes
        capacity_epilogue(blockIdx.x / BPG, out);
    }
}

// ---------------------------------------------------------------------------
extern "C" void kernel_launch(void* const* d_in, const int* in_sizes, int n_in,
                              void* d_out, int out_size) {
    const float4* hs = (const float4*)d_in[0];  // [8, 2048, 2048] f32
    const float* W   = (const float*)d_in[1];   // [8, 2048] f32
    const float* b   = (const float*)d_in[2];   // [8] f32
    float* out = (float*)d_out;

    const int smem = NE * NH / 2 * 8            // W u64 (pair-packed)
                   + TPBK * 9 * 4               // logits
                   + 8 * 4                      // bias
                   + TPBK * 4;                  // argmax
    cudaFuncSetAttribute(router_kernel,
                         cudaFuncAttributeMaxDynamicSharedMemorySize, smem);

    router_kernel<<<NBLK, THREADS, smem>>>(hs, W, b, out);
}